// round 16
// baseline (speedup 1.0000x reference)
#include <cuda_runtime.h>
#include <cuda_fp16.h>
#include <math.h>
#include <stdint.h>

// Problem constants
#define NB   8192
#define DD   1024
#define EE   8
#define HH   4096

// GEMM tiling
#define BM 128
#define BN 128
#define BKH 64
#define A_BYTES (BM * BKH * 2)
#define B_BYTES (BN * BKH * 2)
#define STAGE_BYTES (A_BYTES + B_BYTES)
#define NSTAGE 3
#define SMEM_DYN (NSTAGE * STAGE_BYTES)     // 96 KB -> 2 CTAs/SM

#define G1_NB (HH / BN)                     // 32
#define G1_MB (NB / BM)                     // 64
#define G2_NB (DD / BN)                     // 8

// mega-kernel layout
#define TW1_BLKS 4096
#define TW2_BLKS 4096
#define TR_BLKS  (TW1_BLKS + TW2_BLKS)      // 8192
#define SEG      (128 + G1_NB)              // 160 per M-group
#define SEG_BLKS (G1_MB * SEG)              // 10240
#define G2_BLKS  (G1_MB * G2_NB)            // 512
#define MEGA_BLKS (TR_BLKS + SEG_BLKS + G2_BLKS)   // 18944

// Scratch
__device__ __half g_h2 [(size_t)NB * DD];
__device__ __half g_act[(size_t)NB * HH];
__device__ __half g_w1t[(size_t)HH * DD];
__device__ __half g_w2t[(size_t)DD * HH];
__device__ int    g_tok[G1_MB];
__device__ int    g_g1 [G1_MB];
__device__ int    g_w1c;
__device__ int    g_w2c;

// ---------------------------------------------------------------------------
__device__ __forceinline__ uint32_t smem_u32(const void* p) {
    uint32_t a;
    asm("{ .reg .u64 t; cvta.to.shared.u64 t, %1; cvt.u32.u64 %0, t; }" : "=r"(a) : "l"(p));
    return a;
}
#define CP_ASYNC16(dst, src) \
    asm volatile("cp.async.cg.shared.global [%0], [%1], 16;" :: "r"(dst), "l"(src))
#define CP_COMMIT() asm volatile("cp.async.commit_group;" ::: "memory")
#define CP_WAIT(n)  asm volatile("cp.async.wait_group %0;" :: "n"(n) : "memory")

#define LDSM4(d0, d1, d2, d3, addr) \
    asm volatile("ldmatrix.sync.aligned.m8n8.x4.shared.b16 {%0,%1,%2,%3}, [%4];" \
        : "=r"(d0), "=r"(d1), "=r"(d2), "=r"(d3) : "r"(addr))

__device__ __forceinline__ void mma16816(float* d, const uint32_t* a, const uint32_t* b) {
    asm volatile(
        "mma.sync.aligned.m16n8k16.row.col.f32.f16.f16.f32 "
        "{%0,%1,%2,%3}, {%4,%5,%6,%7}, {%8,%9}, {%0,%1,%2,%3};"
        : "+f"(d[0]), "+f"(d[1]), "+f"(d[2]), "+f"(d[3])
        : "r"(a[0]), "r"(a[1]), "r"(a[2]), "r"(a[3]), "r"(b[0]), "r"(b[1]));
}

__device__ __forceinline__ float gelu_f(float v) {
    const float c = 0.7978845608028654f;
    float u = c * (v + 0.044715f * v * v * v);
    return 0.5f * v * (1.0f + tanhf(u));
}

__device__ __forceinline__ void spin_until(volatile int* p, int target) {
    while (*p != target) { }
}

// ---------------------------------------------------------------------------
template<int ROWS>
__device__ __forceinline__ void stage_copy(const __half* __restrict__ g, int ldg,
                                           uint32_t sbase, int tid) {
    #pragma unroll
    for (int p = 0; p < ROWS * 8 / 256; p++) {
        const int idx = tid + p * 256;
        const int row = idx >> 3;
        const int c   = idx & 7;
        const uint32_t dst = sbase + (uint32_t)row * 128 + (uint32_t)((c ^ (row & 7)) << 4);
        CP_ASYNC16(dst, (const char*)g + (size_t)row * ldg * 2 + (size_t)c * 16);
    }
}

// ---------------------------------------------------------------------------
// GEMM body (unchanged schedule): 8 warps, warp tile 64x32, 3 stages
// ---------------------------------------------------------------------------
template<int Kc, int Nc, int EPI>
__device__ __forceinline__ void gemm_body(
    const __half* __restrict__ A, const __half* __restrict__ Bt,
    const float* __restrict__ bias, void* __restrict__ Cv,
    size_t bm, size_t bn, char* sm, int tid)
{
    const int wid = tid >> 5;
    const int lid = tid & 31;
    const int q   = lid >> 2;
    const int j   = lid & 3;
    const int m0  = (wid >> 2) * 64;
    const int n0  = (wid & 3) * 32;

    const __half* Ab = A  + bm * Kc;
    const __half* Bb = Bt + bn * Kc;

    const uint32_t sb0 = smem_u32(sm);
    const int KT = Kc / BKH;

    const int seg = lid >> 3;
    const int rr  = lid & 7;
    const int khA = seg >> 1;
    const int khB = seg & 1;
    uint32_t aAddr[4], bAddr[2];
    #pragma unroll
    for (int mi = 0; mi < 4; mi++)
        aAddr[mi] = (uint32_t)(m0 + mi * 16 + (seg & 1) * 8 + rr) * 128;
    #pragma unroll
    for (int p = 0; p < 2; p++)
        bAddr[p] = (uint32_t)A_BYTES + (uint32_t)(n0 + p * 16 + (seg >> 1) * 8 + rr) * 128;

    float acc[4][4][4];
    #pragma unroll
    for (int mi = 0; mi < 4; mi++)
        #pragma unroll
        for (int ni = 0; ni < 4; ni++)
            #pragma unroll
            for (int v = 0; v < 4; v++) acc[mi][ni][v] = 0.0f;

    #pragma unroll
    for (int s = 0; s < NSTAGE - 1; s++) {
        const uint32_t sa = sb0 + (uint32_t)s * STAGE_BYTES;
        stage_copy<BM>(Ab + (size_t)s * BKH, Kc, sa, tid);
        stage_copy<BN>(Bb + (size_t)s * BKH, Kc, sa + A_BYTES, tid);
        CP_COMMIT();
    }

    for (int kt = 0; kt < KT; kt++) {
        CP_WAIT(NSTAGE - 2);
        __syncthreads();

        if (kt + NSTAGE - 1 < KT) {
            const uint32_t sa = sb0 + (uint32_t)((kt + NSTAGE - 1) % NSTAGE) * STAGE_BYTES;
            stage_copy<BM>(Ab + (size_t)(kt + NSTAGE - 1) * BKH, Kc, sa, tid);
            stage_copy<BN>(Bb + (size_t)(kt + NSTAGE - 1) * BKH, Kc, sa + A_BYTES, tid);
        }
        CP_COMMIT();

        const uint32_t S = sb0 + (uint32_t)(kt % NSTAGE) * STAGE_BYTES;

        #pragma unroll
        for (int ks = 0; ks < BKH / 16; ks++) {
            const uint32_t cA = (uint32_t)(((2 * ks + khA) ^ rr) << 4);
            const uint32_t cB = (uint32_t)(((2 * ks + khB) ^ rr) << 4);

            uint32_t a[4][4];
            #pragma unroll
            for (int mi = 0; mi < 4; mi++)
                LDSM4(a[mi][0], a[mi][1], a[mi][2], a[mi][3], S + aAddr[mi] + cA);

            uint32_t b[2][4];
            #pragma unroll
            for (int p = 0; p < 2; p++)
                LDSM4(b[p][0], b[p][1], b[p][2], b[p][3], S + bAddr[p] + cB);

            #pragma unroll
            for (int mi = 0; mi < 4; mi++)
                #pragma unroll
                for (int ni = 0; ni < 4; ni++) {
                    uint32_t bb[2] = { b[ni >> 1][(ni & 1) * 2],
                                       b[ni >> 1][(ni & 1) * 2 + 1] };
                    mma16816(acc[mi][ni], a[mi], bb);
                }
        }
    }

    const size_t row0 = bm + m0 + q;
    const int    col0 = (int)bn + n0 + 2 * j;

    #pragma unroll
    for (int ni = 0; ni < 4; ni++) {
        const int col = col0 + 8 * ni;
        float bv0 = 0.f, bv1 = 0.f;
        if (EPI == 1) { bv0 = __ldg(bias + col); bv1 = __ldg(bias + col + 1); }
        #pragma unroll
        for (int mi = 0; mi < 4; mi++) {
            const size_t r = row0 + 16 * mi;
            if (EPI == 1) {
                __half* Ch = (__half*)Cv;
                *(half2*)(Ch + r * Nc + col) =
                    __floats2half2_rn(gelu_f(acc[mi][ni][0] + bv0),
                                      gelu_f(acc[mi][ni][1] + bv1));
                *(half2*)(Ch + (r + 8) * Nc + col) =
                    __floats2half2_rn(gelu_f(acc[mi][ni][2] + bv0),
                                      gelu_f(acc[mi][ni][3] + bv1));
            } else {
                float* Cf = (float*)Cv;
                float2 o0 = *(const float2*)(Cf + r * Nc + col);
                float2 o1 = *(const float2*)(Cf + (r + 8) * Nc + col);
                o0.x += acc[mi][ni][0];  o0.y += acc[mi][ni][1];
                o1.x += acc[mi][ni][2];  o1.y += acc[mi][ni][3];
                *(float2*)(Cf + r * Nc + col) = o0;
                *(float2*)(Cf + (r + 8) * Nc + col) = o1;
            }
        }
    }
}

// ---------------------------------------------------------------------------
// Paired block-wide sum (sbuf2 carved from dynamic smem)
// ---------------------------------------------------------------------------
__device__ __forceinline__ float2 blk_sum2(float a, float b, float2* sbuf2) {
    #pragma unroll
    for (int o = 16; o > 0; o >>= 1) {
        a += __shfl_xor_sync(0xffffffffu, a, o);
        b += __shfl_xor_sync(0xffffffffu, b, o);
    }
    const int w = threadIdx.x >> 5;
    if ((threadIdx.x & 31) == 0) sbuf2[w] = make_float2(a, b);
    __syncthreads();
    if (threadIdx.x < 32) {
        float xa = 0.f, xb = 0.f;
        if (threadIdx.x < 8) { float2 v = sbuf2[threadIdx.x]; xa = v.x; xb = v.y; }
        #pragma unroll
        for (int o = 4; o > 0; o >>= 1) {
            xa += __shfl_xor_sync(0xffffffffu, xa, o);
            xb += __shfl_xor_sync(0xffffffffu, xb, o);
        }
        if (threadIdx.x == 0) sbuf2[0] = make_float2(xa, xb);
    }
    __syncthreads();
    float2 r = sbuf2[0];
    __syncthreads();
    return r;
}

// ---------------------------------------------------------------------------
// reset kernel: zero dependency counters (each call, graph-replay safe)
// ---------------------------------------------------------------------------
__global__ void reset_kernel() {
    const int tid = threadIdx.x;
    if (tid < G1_MB) { g_tok[tid] = 0; g_g1[tid] = 0; }
    if (tid == 64) g_w1c = 0;
    if (tid == 65) g_w2c = 0;
}

// ---------------------------------------------------------------------------
// Mega kernel: transposes -> interleaved (token | GEMM1) groups -> GEMM2
// ---------------------------------------------------------------------------
__global__ __launch_bounds__(256, 2) void mega_kernel(
    const float* __restrict__ x, const int* __restrict__ ids,
    const float* __restrict__ lut,
    const float* __restrict__ ln1g, const float* __restrict__ ln1b,
    const float* __restrict__ ln2g, const float* __restrict__ ln2b,
    const float* __restrict__ rw,  const float* __restrict__ rb,
    const float* __restrict__ bias2,
    const float* __restrict__ w1,  const float* __restrict__ b1,
    const float* __restrict__ w2,  float* __restrict__ out)
{
    extern __shared__ __align__(16) char sm[];
    const int bid = blockIdx.x;
    const int tid = threadIdx.x;

    if (bid < TR_BLKS) {
        // ---------------- transpose path ----------------
        float (*tile)[33] = (float(*)[33])sm;
        const float* in;  __half* o;  int rows, cols, bx, by;
        int* donec;
        if (bid < TW1_BLKS) {
            in = w1; o = g_w1t; rows = DD; cols = HH;
            bx = bid & 127;  by = bid >> 7;  donec = &g_w1c;
        } else {
            const int i2 = bid - TW1_BLKS;
            in = w2; o = g_w2t; rows = HH; cols = DD;
            bx = i2 & 31;    by = i2 >> 5;   donec = &g_w2c;
        }
        const int tx = tid & 31, ty = tid >> 5;
        int xx = bx * 32 + tx;
        int yy = by * 32 + ty;
        #pragma unroll
        for (int jj = 0; jj < 32; jj += 8)
            tile[ty + jj][tx] = in[(size_t)(yy + jj) * cols + xx];
        __syncthreads();
        xx = by * 32 + tx;
        yy = bx * 32 + ty;
        #pragma unroll
        for (int jj = 0; jj < 32; jj += 8)
            o[(size_t)(yy + jj) * rows + xx] = __float2half(tile[tx][ty + jj]);
        __threadfence();
        __syncthreads();
        if (tid == 0) atomicAdd(donec, 1);
        return;
    }

    if (bid < TR_BLKS + SEG_BLKS) {
        const int segidx = bid - TR_BLKS;
        const int grp = segidx / SEG;
        const int r   = segidx % SEG;

        if (r < 128) {
            // ---------------- token path ----------------
            float*  s_lut = (float*)sm;                    // 32 KB
            float*  s_h   = (float*)(sm + 32768);          // 4 KB
            float2* sbuf2 = (float2*)(sm + 36864);         // 64 B
            float*  rp    = (float*)(sm + 36928);          // 256 B
            float*  slog  = (float*)(sm + 37184);          // 32 B

            const int t = grp * 128 + r;

            const int sid = __ldg(ids + t);
            const float* lbase = lut + (size_t)sid * (size_t)(EE * DD);
            const uint32_t slut = smem_u32(s_lut);
            #pragma unroll
            for (int e = 0; e < EE; e++)
                CP_ASYNC16(slut + (uint32_t)(e * DD + tid * 4) * 4,
                           lbase + (size_t)e * DD + tid * 4);
            CP_COMMIT();

            const float4 xv = ((const float4*)(x + (size_t)t * DD))[tid];

            float s1 = xv.x + xv.y + xv.z + xv.w;
            float s2 = xv.x*xv.x + xv.y*xv.y + xv.z*xv.z + xv.w*xv.w;
            const float2 m1 = blk_sum2(s1, s2, sbuf2);
            const float mu   = m1.x * (1.0f / DD);
            const float var  = m1.y * (1.0f / DD) - mu * mu;
            const float rstd = rsqrtf(var + 1e-5f);

            float4 g1 = ((const float4*)ln1g)[tid];
            float4 c1 = ((const float4*)ln1b)[tid];
            float h[4];
            h[0] = (xv.x - mu) * rstd * g1.x + c1.x;
            h[1] = (xv.y - mu) * rstd * g1.y + c1.y;
            h[2] = (xv.z - mu) * rstd * g1.z + c1.z;
            h[3] = (xv.w - mu) * rstd * g1.w + c1.w;

            ((float4*)s_h)[tid] = make_float4(h[0], h[1], h[2], h[3]);
            __syncthreads();

            float p[EE];
            #pragma unroll
            for (int e = 0; e < EE; e++) p[e] = 0.0f;
            #pragma unroll
            for (int jj = 0; jj < 4; jj++) {
                const int d = tid + 256 * jj;
                const float hd = s_h[d];
                const float4* row = (const float4*)(rw + (size_t)d * EE);
                const float4 r0 = row[0], r1 = row[1];
                p[0] += hd * r0.x;  p[1] += hd * r0.y;
                p[2] += hd * r0.z;  p[3] += hd * r0.w;
                p[4] += hd * r1.x;  p[5] += hd * r1.y;
                p[6] += hd * r1.z;  p[7] += hd * r1.w;
            }
            #pragma unroll
            for (int e = 0; e < EE; e++) {
                float v = p[e];
                #pragma unroll
                for (int o = 16; o > 0; o >>= 1) v += __shfl_xor_sync(0xffffffffu, v, o);
                if ((tid & 31) == 0) rp[e * 8 + (tid >> 5)] = v;
            }
            __syncthreads();
            if (tid < EE) {
                float v = rb[tid];
                #pragma unroll
                for (int w = 0; w < 8; w++) v += rp[tid * 8 + w];
                slog[tid] = v;
            }
            __syncthreads();

            float rv[EE];
            float mx = -1e30f;
            #pragma unroll
            for (int e = 0; e < EE; e++) mx = fmaxf(mx, slog[e]);
            float den = 0.0f;
            #pragma unroll
            for (int e = 0; e < EE; e++) { rv[e] = __expf(slog[e] - mx); den += rv[e]; }
            const float inv = 1.0f / den;
            #pragma unroll
            for (int e = 0; e < EE; e++) rv[e] *= inv;

            float t1 = h[0] + h[1] + h[2] + h[3];
            float t2 = h[0]*h[0] + h[1]*h[1] + h[2]*h[2] + h[3]*h[3];
            const float2 m2 = blk_sum2(t1, t2, sbuf2);
            const float mu2   = m2.x * (1.0f / DD);
            const float var2  = m2.y * (1.0f / DD) - mu2 * mu2;
            const float rstd2 = rsqrtf(var2 + 1e-5f);

            float4 g2 = ((const float4*)ln2g)[tid];
            float4 c2 = ((const float4*)ln2b)[tid];
            half2* h2p = (half2*)(g_h2 + (size_t)t * DD);
            h2p[tid * 2]     = __floats2half2_rn((h[0] - mu2) * rstd2 * g2.x + c2.x,
                                                 (h[1] - mu2) * rstd2 * g2.y + c2.y);
            h2p[tid * 2 + 1] = __floats2half2_rn((h[2] - mu2) * rstd2 * g2.z + c2.z,
                                                 (h[3] - mu2) * rstd2 * g2.w + c2.w);

            CP_WAIT(0);
            __syncthreads();

            float4 acc = make_float4(0.f, 0.f, 0.f, 0.f);
            #pragma unroll
            for (int e = 0; e < EE; e++) {
                const float4 lv = ((const float4*)s_lut)[e * (DD / 4) + tid];
                acc.x += rv[e] * lv.x;  acc.y += rv[e] * lv.y;
                acc.z += rv[e] * lv.z;  acc.w += rv[e] * lv.w;
            }

            float4 b2v = ((const float4*)bias2)[tid];
            float4 o;
            o.x = xv.x + acc.x + b2v.x;
            o.y = xv.y + acc.y + b2v.y;
            o.z = xv.z + acc.z + b2v.z;
            o.w = xv.w + acc.w + b2v.w;
            ((float4*)(out + (size_t)t * DD))[tid] = o;

            __threadfence();
            __syncthreads();
            if (tid == 0) atomicAdd(&g_tok[grp], 1);
        } else {
            // ---------------- GEMM1 path ----------------
            const int bn_i = r - 128;
            if (tid == 0) {
                spin_until(&g_tok[grp], 128);
                spin_until(&g_w1c, TW1_BLKS);
            }
            __syncthreads();
            __threadfence();
            gemm_body<DD, HH, 1>(g_h2, g_w1t, b1, g_act,
                                 (size_t)grp * BM, (size_t)bn_i * BN, sm, tid);
            __threadfence();
            __syncthreads();
            if (tid == 0) atomicAdd(&g_g1[grp], 1);
        }
        return;
    }

    // ---------------- GEMM2 path ----------------
    {
        const int b2i = bid - TR_BLKS - SEG_BLKS;
        const int grp  = b2i >> 3;               // /G2_NB
        const int bn_i = b2i & (G2_NB - 1);
        if (tid == 0) {
            spin_until(&g_g1[grp], G1_NB);
            spin_until(&g_w2c, TW2_BLKS);
        }
        __syncthreads();
        __threadfence();
        gemm_body<HH, DD, 2>(g_act, g_w2t, nullptr, out,
                             (size_t)grp * BM, (size_t)bn_i * BN, sm, tid);
    }
}

// ---------------------------------------------------------------------------
// launch
// ---------------------------------------------------------------------------
extern "C" void kernel_launch(void* const* d_in, const int* in_sizes, int n_in,
                              void* d_out, int out_size)
{
    const float* x    = (const float*)d_in[0];
    const int*   ids  = (const int*)  d_in[1];
    const float* lut  = (const float*)d_in[2];
    const float* ln1g = (const float*)d_in[3];
    const float* ln1b = (const float*)d_in[4];
    const float* ln2g = (const float*)d_in[5];
    const float* ln2b = (const float*)d_in[6];
    const float* rw   = (const float*)d_in[7];
    const float* rb   = (const float*)d_in[8];
    const float* w1   = (const float*)d_in[9];
    const float* b1   = (const float*)d_in[10];
    const float* w2   = (const float*)d_in[11];
    const float* b2   = (const float*)d_in[12];
    float* out = (float*)d_out;

    cudaFuncSetAttribute(mega_kernel, cudaFuncAttributeMaxDynamicSharedMemorySize, SMEM_DYN);

    reset_kernel<<<1, 256>>>();
    mega_kernel<<<MEGA_BLKS, 256, SMEM_DYN>>>(
        x, ids, lut, ln1g, ln1b, ln2g, ln2b, rw, rb, b2, w1, b1, w2, out);
}